// round 10
// baseline (speedup 1.0000x reference)
#include <cuda_runtime.h>
#include <cstdint>
#include <math.h>

#define B   64
#define M   1024
#define W   64
#define R   4
#define D   512
#define IF  471

// ---------------- scratch ----------------
__device__ __align__(16) float g_keys[B * R * W];
__device__ float g_kstr[B * R];
__device__ float g_knorm[B * R];
__device__ __align__(16) float g_wkey[B * W];
__device__ float g_wknorm[B];
__device__ float g_ws[B];
__device__ __align__(16) float g_erase[B * W];
__device__ __align__(16) float g_wvec[B * W];
__device__ float g_ag[B], g_wg[B];
__device__ float g_rm[B * R * 3];
__device__ float g_usage[B * M];
__device__ float g_wcd[B * M];
__device__ float g_ww[B * M];
__device__ float g_d[B * R * M];        // e = exp(d - kstr)
__device__ float g_esum[B * R];
__device__ __align__(16) float g_fw[B * R * M];
__device__ __align__(16) float g_bwp[B * 16 * R * M];
__device__ __align__(16) float g_newmem[B * M * W];

// ---------------- helpers ----------------
__device__ __forceinline__ float sigmoidf_(float x) { return 1.0f / (1.0f + expf(-x)); }
__device__ __forceinline__ float softplusf_(float x) { return (x > 20.0f) ? x : log1pf(expf(x)); }

__device__ __forceinline__ unsigned long long pack2_(float lo, float hi) {
    unsigned long long r;
    asm("mov.b64 %0, {%1, %2};" : "=l"(r) : "f"(lo), "f"(hi));
    return r;
}
__device__ __forceinline__ void unpack2_(unsigned long long v, float& lo, float& hi) {
    asm("mov.b64 {%0, %1}, %2;" : "=f"(lo), "=f"(hi) : "l"(v));
}
__device__ __forceinline__ unsigned long long fma2_(unsigned long long a, unsigned long long b, unsigned long long c) {
    unsigned long long d;
    asm("fma.rn.f32x2 %0, %1, %2, %3;" : "=l"(d) : "l"(a), "l"(b), "l"(c));
    return d;
}
__device__ __forceinline__ unsigned long long mul2_(unsigned long long a, unsigned long long b) {
    unsigned long long d;
    asm("mul.rn.f32x2 %0, %1, %2;" : "=l"(d) : "l"(a), "l"(b));
    return d;
}
__device__ __forceinline__ unsigned long long add2_(unsigned long long a, unsigned long long b) {
    unsigned long long d;
    asm("add.rn.f32x2 %0, %1, %2;" : "=l"(d) : "l"(a), "l"(b));
    return d;
}

__device__ __forceinline__ float warpMax_(float v) {
#pragma unroll
    for (int o = 16; o; o >>= 1) v = fmaxf(v, __shfl_xor_sync(0xffffffffu, v, o));
    return v;
}
__device__ __forceinline__ float warpSum_(float v) {
#pragma unroll
    for (int o = 16; o; o >>= 1) v += __shfl_xor_sync(0xffffffffu, v, o);
    return v;
}
__device__ __forceinline__ float blockMax_(float v, float* sh) {
    v = warpMax_(v);
    if ((threadIdx.x & 31) == 0) sh[threadIdx.x >> 5] = v;
    __syncthreads();
    float r = sh[threadIdx.x & 31];
    r = warpMax_(r);
    __syncthreads();
    return r;
}
__device__ __forceinline__ float blockSum_(float v, float* sh) {
    v = warpSum_(v);
    if ((threadIdx.x & 31) == 0) sh[threadIdx.x >> 5] = v;
    __syncthreads();
    float r = sh[threadIdx.x & 31];
    r = warpSum_(r);
    __syncthreads();
    return r;
}

// ---------------- K1: iface GEMV (2-way D-split) + parse + usage ----------------
__global__ __launch_bounds__(1024) void k_ifprep(const float* __restrict__ xi,
                                                 const float* __restrict__ Wm,
                                                 const float* __restrict__ bW,
                                                 const float* __restrict__ read_weights,
                                                 const float* __restrict__ write_weights,
                                                 const float* __restrict__ usage_vector) {
    int b = blockIdx.x, t = threadIdx.x;
    __shared__ float xs[D];
    __shared__ float f[IF + 1];
    __shared__ float fpart[512];
    if (t < D) xs[t] = xi[b * D + t];
    __syncthreads();
    {
        int j = t & 511, half = t >> 9;
        if (j < IF) {
            const float* Wp = Wm + (size_t)(half * 256) * IF + j;
            const float* xh = xs + half * 256;
            float acc = 0.0f;
#pragma unroll 8
            for (int i = 0; i < 256; i++) acc = fmaf(xh[i], Wp[(size_t)i * IF], acc);
            if (half) fpart[j] = acc;
            else      f[j] = acc;
        }
        __syncthreads();
        if (half == 0 && j < IF) f[j] = f[j] + fpart[j] + bW[j];
        __syncthreads();
    }

    if (t < 256) g_keys[b * 256 + t] = f[t];
    if (t >= 256 && t < 320) { int i = t - 256; g_wkey[b * W + i] = f[260 + i]; }
    if (t >= 320 && t < 384) { int i = t - 320; g_erase[b * W + i] = sigmoidf_(f[325 + i]); }
    if (t >= 384 && t < 448) { int i = t - 384; g_wvec[b * W + i] = f[389 + i]; }
    if (t < 4) {
        float x = f[256 + t];
        g_kstr[b * 4 + t] = softplusf_(1.0f + fmaxf(x, 0.0f));
        float s = 0.0f;
        for (int i = 0; i < W; i++) { float v = f[t * W + i]; s = fmaf(v, v, s); }
        g_knorm[b * 4 + t] = sqrtf(s);
        g_esum[b * 4 + t] = 0.0f;
    }
    if (t == 4) {
        float x = f[324];
        g_ws[b] = softplusf_(1.0f + fmaxf(x, 0.0f));
        float s = 0.0f;
        for (int i = 0; i < W; i++) { float v = f[260 + i]; s = fmaf(v, v, s); }
        g_wknorm[b] = sqrtf(s);
    }
    if (t == 5) g_ag[b] = sigmoidf_(f[457]);
    if (t == 6) g_wg[b] = sigmoidf_(f[458]);
    if (t >= 8 && t < 11) {
        int j = t - 8;
        float v[4], mx = -1e30f;
        for (int rr = 0; rr < 4; rr++) { v[rr] = f[458 + rr * 3 + j]; mx = fmaxf(mx, v[rr]); }
        float s = 0.0f;
        for (int rr = 0; rr < 4; rr++) { v[rr] = expf(v[rr] - mx); s += v[rr]; }
        for (int rr = 0; rr < 4; rr++) g_rm[b * 12 + rr * 3 + j] = v[rr] / s;
    }

    float fg0 = sigmoidf_(f[453]), fg1 = sigmoidf_(f[454]);
    float fg2 = sigmoidf_(f[455]), fg3 = sigmoidf_(f[456]);
    for (int m = t; m < M; m += 1024) {
        float uv = usage_vector[b * M + m];
        float wwo = write_weights[b * M + m];
        float u = uv + (1.0f - uv) * wwo;
        float psi = (1.0f - fg0 * read_weights[(b * 4 + 0) * M + m])
                  * (1.0f - fg1 * read_weights[(b * 4 + 1) * M + m])
                  * (1.0f - fg2 * read_weights[(b * 4 + 2) * M + m])
                  * (1.0f - fg3 * read_weights[(b * 4 + 3) * M + m]);
        g_usage[b * M + m] = u * psi;
    }
}

// ---------------- K2: write-content distances (grid 8x64) ----------------
__global__ __launch_bounds__(256) void k_wc(const float* __restrict__ memory) {
    int slab = blockIdx.x, b = blockIdx.y, t = threadIdx.x;
    __shared__ float4 key_s[16];
    __shared__ float sc;
    if (t < 16) key_s[t] = ((const float4*)(g_wkey + b * W))[t];
    if (t == 16) sc = g_ws[b] / (g_wknorm[b] + 1e-6f);
    __syncthreads();
    int row16 = t >> 4, l16 = t & 15;
    const float4* mem4 = (const float4*)(memory + (size_t)b * M * W);
#pragma unroll 2
    for (int pass = 0; pass < 8; pass++) {
        int m = slab * 128 + pass * 16 + row16;
        float4 v = mem4[m * 16 + l16];
        float4 k = key_s[l16];
        float dot = v.x * k.x + v.y * k.y + v.z * k.z + v.w * k.w;
        float ns  = v.x * v.x + v.y * v.y + v.z * v.z + v.w * v.w;
#pragma unroll
        for (int o = 8; o; o >>= 1) {
            dot += __shfl_xor_sync(0xffffffffu, dot, o);
            ns  += __shfl_xor_sync(0xffffffffu, ns, o);
        }
        if (l16 == 0) g_wcd[b * M + m] = dot * sc / (sqrtf(ns) + 1e-6f);
    }
}

// ---------------- K3: softmax(wcd) + allocation sort + ww ----------------
__global__ __launch_bounds__(1024) void k_weights() {
    int b = blockIdx.x, t = threadIdx.x;
    int lane = t & 31, warp = t >> 5;
    __shared__ float dv[M];
    __shared__ float red[32];
    __shared__ unsigned long long ks[M];
    __shared__ float wtot[32];

    {
        float x = g_wcd[b * M + t];
        float mx = blockMax_(x, red);
        float e = expf(x - mx);
        float sm = blockSum_(e, red);
        dv[t] = e / sm;
    }

    float u = 1e-6f + (1.0f - 1e-6f) * g_usage[b * M + t];
    unsigned long long v = ((unsigned long long)__float_as_uint(u) << 32) | (unsigned)t;
#pragma unroll
    for (int k = 2; k <= 32; k <<= 1) {
#pragma unroll
        for (int j = k >> 1; j > 0; j >>= 1) {
            unsigned long long c = __shfl_xor_sync(0xffffffffu, v, j);
            bool keepMin = ((t & j) == 0) == ((t & k) == 0);
            bool less = v < c;
            v = (less == keepMin) ? v : c;
        }
    }
    ks[t] = v;
    __syncthreads();
#pragma unroll
    for (int k = 64; k <= M; k <<= 1) {
        for (int j = k >> 1; j >= 32; j >>= 1) {
            unsigned long long a = ks[t];
            unsigned long long c = ks[t ^ j];
            bool keepMin = ((t & j) == 0) == ((t & k) == 0);
            bool less = a < c;
            v = (less == keepMin) ? a : c;
            __syncthreads();
            ks[t] = v;
            __syncthreads();
        }
#pragma unroll
        for (int j = 16; j > 0; j >>= 1) {
            unsigned long long c = __shfl_xor_sync(0xffffffffu, v, j);
            bool keepMin = ((t & j) == 0) == ((t & k) == 0);
            bool less = v < c;
            v = (less == keepMin) ? v : c;
        }
        if (k < M) { ks[t] = v; __syncthreads(); }
    }
    float su = __uint_as_float((unsigned)(v >> 32));
    float p = su;
#pragma unroll
    for (int o = 1; o < 32; o <<= 1) {
        float q = __shfl_up_sync(0xffffffffu, p, o);
        if (lane >= o) p *= q;
    }
    if (lane == 31) wtot[warp] = p;
    __syncthreads();
    if (warp == 0) {
        float q = wtot[lane];
#pragma unroll
        for (int o = 1; o < 32; o <<= 1) {
            float rr = __shfl_up_sync(0xffffffffu, q, o);
            if (lane >= o) q *= rr;
        }
        wtot[lane] = q;
    }
    __syncthreads();
    if (warp > 0) p *= wtot[warp - 1];

    int idx = (int)(v & 0xffffffffULL);
    float alloc = (1.0f - su) * p;
    float ag = g_ag[b], wg = g_wg[b];
    g_ww[b * M + idx] = wg * (ag * alloc + (1.0f - ag) * dv[idx]);
}

// ---------------- K4: fused link + memory-update kernel (grid 24xB) [PROFILED] ----------------
// blocks x<16: link row-tile mt=x; blocks x>=16: memup slab = x-16
__global__ __launch_bounds__(256) void k_linkmem(const float* __restrict__ link,
                                                 const float* __restrict__ precedence,
                                                 const float* __restrict__ read_weights,
                                                 const float* __restrict__ memory) {
    __shared__ __align__(16) char smraw[9472];
    int b = blockIdx.y;
    int t = threadIdx.x;

    if (blockIdx.x < 16) {
        // ======================= LINK PATH =======================
        int mt = blockIdx.x;
        int warp = t >> 5, lane = t & 31;
        float* ww_row = (float*)smraw;                         // 256 B
        float4* rw_row = (float4*)(smraw + 256);               // 1 KB
        float (*fw_s)[4][64] = (float (*)[4][64])(smraw + 1280); // 8 KB

        if (t < 64) ww_row[t] = g_ww[b * M + mt * 64 + t];
        {
            int r = t >> 6, mi = t & 63;
            ((float*)rw_row)[mi * 4 + r] = read_weights[(b * 4 + r) * M + mt * 64 + mi];
        }

        int n0 = t * 4;
        float4 wwn = *(const float4*)&g_ww[b * M + n0];
        float4 pnf = *(const float4*)&precedence[b * M + n0];
        unsigned long long a01 = pack2_(1.0f - wwn.x, 1.0f - wwn.y);
        unsigned long long a23 = pack2_(1.0f - wwn.z, 1.0f - wwn.w);
        unsigned long long pn01 = pack2_(pnf.x, pnf.y);
        unsigned long long pn23 = pack2_(pnf.z, pnf.w);
        unsigned long long rwn01[4], rwn23[4];
#pragma unroll
        for (int rr = 0; rr < 4; rr++) {
            float4 rv = *(const float4*)&read_weights[(b * 4 + rr) * M + n0];
            rwn01[rr] = pack2_(rv.x, rv.y);
            rwn23[rr] = pack2_(rv.z, rv.w);
        }
        unsigned long long bwa01[4] = {0ull, 0ull, 0ull, 0ull};
        unsigned long long bwa23[4] = {0ull, 0ull, 0ull, 0ull};

        const ulonglong2* Lp = (const ulonglong2*)(link + (size_t)b * M * M + (size_t)(mt * 64) * M) + t;
        __syncthreads();

        ulonglong2 L = *Lp;
#pragma unroll 2
        for (int mi = 0; mi < 64; mi++) {
            ulonglong2 Ln;
            if (mi < 63) Ln = Lp[256 * (mi + 1)];
            float wwm = ww_row[mi];
            float4 rr4 = rw_row[mi];
            unsigned long long wwm2 = pack2_(wwm, wwm);
            unsigned long long nww2 = pack2_(-wwm, -wwm);
            unsigned long long c01 = add2_(a01, nww2);
            unsigned long long c23 = add2_(a23, nww2);
            unsigned long long nl01 = fma2_(L.x, c01, mul2_(wwm2, pn01));
            unsigned long long nl23 = fma2_(L.y, c23, mul2_(wwm2, pn23));

            float f0, f1, f2, f3;
            {
                float lo, hi;
                unsigned long long p0 = fma2_(nl23, rwn23[0], mul2_(nl01, rwn01[0]));
                unpack2_(p0, lo, hi); f0 = lo + hi;
                unsigned long long p1 = fma2_(nl23, rwn23[1], mul2_(nl01, rwn01[1]));
                unpack2_(p1, lo, hi); f1 = lo + hi;
                unsigned long long p2 = fma2_(nl23, rwn23[2], mul2_(nl01, rwn01[2]));
                unpack2_(p2, lo, hi); f2 = lo + hi;
                unsigned long long p3 = fma2_(nl23, rwn23[3], mul2_(nl01, rwn01[3]));
                unpack2_(p3, lo, hi); f3 = lo + hi;
            }
            {
                unsigned long long r2;
                r2 = pack2_(rr4.x, rr4.x);
                bwa01[0] = fma2_(nl01, r2, bwa01[0]); bwa23[0] = fma2_(nl23, r2, bwa23[0]);
                r2 = pack2_(rr4.y, rr4.y);
                bwa01[1] = fma2_(nl01, r2, bwa01[1]); bwa23[1] = fma2_(nl23, r2, bwa23[1]);
                r2 = pack2_(rr4.z, rr4.z);
                bwa01[2] = fma2_(nl01, r2, bwa01[2]); bwa23[2] = fma2_(nl23, r2, bwa23[2]);
                r2 = pack2_(rr4.w, rr4.w);
                bwa01[3] = fma2_(nl01, r2, bwa01[3]); bwa23[3] = fma2_(nl23, r2, bwa23[3]);
            }

            float g01 = (lane & 1) ? f0 : f1;
            g01 = __shfl_xor_sync(0xffffffffu, g01, 1);
            float a01s = ((lane & 1) ? f1 : f0) + g01;
            float g23 = (lane & 1) ? f2 : f3;
            g23 = __shfl_xor_sync(0xffffffffu, g23, 1);
            float a23s = ((lane & 1) ? f3 : f2) + g23;
            float gx = (lane & 2) ? a01s : a23s;
            gx = __shfl_xor_sync(0xffffffffu, gx, 2);
            float c = ((lane & 2) ? a23s : a01s) + gx;
            c += __shfl_xor_sync(0xffffffffu, c, 4);
            c += __shfl_xor_sync(0xffffffffu, c, 8);
            c += __shfl_xor_sync(0xffffffffu, c, 16);
            if (lane < 4) fw_s[warp][lane][mi] = c;
            L = Ln;
        }
        __syncthreads();
        {
            int rr = t >> 6, mi = t & 63;
            float s = 0.0f;
#pragma unroll
            for (int w = 0; w < 8; w++) s += fw_s[w][rr][mi];
            g_fw[(b * 4 + rr) * M + mt * 64 + mi] = s;
        }
#pragma unroll
        for (int rr = 0; rr < 4; rr++) {
            ulonglong2 s; s.x = bwa01[rr]; s.y = bwa23[rr];
            *(ulonglong2*)&g_bwp[((b * 16 + mt) * 4 + rr) * M + n0] = s;
        }
    } else {
        // ======================= MEMUP PATH =======================
        int slab = blockIdx.x - 16;
        float* ww_s = (float*)smraw;                      // 512 B
        float4* rk_s = (float4*)(smraw + 512);            // 1 KB
        float4* e_s = (float4*)(smraw + 1536);            // 256 B
        float4* wv_s = (float4*)(smraw + 1792);           // 256 B
        float* sk_s = (float*)(smraw + 2048);             // 16 B
        float* kst_s = (float*)(smraw + 2064);            // 16 B
        float* spart = (float*)(smraw + 2080);            // 256 B

        if (t < 128) ww_s[t] = g_ww[b * M + slab * 128 + t];
        if (t >= 128 && t < 192) rk_s[t - 128] = ((const float4*)(g_keys + b * 256))[t - 128];
        if (t >= 192 && t < 208) e_s[t - 192] = ((const float4*)(g_erase + b * W))[t - 192];
        if (t >= 208 && t < 224) wv_s[t - 208] = ((const float4*)(g_wvec + b * W))[t - 208];
        if (t >= 224 && t < 228) {
            int r = t - 224;
            float kst = g_kstr[b * 4 + r];
            sk_s[r] = kst / (g_knorm[b * 4 + r] + 1e-6f);
            kst_s[r] = kst;
        }
        __syncthreads();

        int row16 = t >> 4, l16 = t & 15;
        const float4* mem4 = (const float4*)(memory + (size_t)b * M * W);
        float4* nm4 = (float4*)(g_newmem + (size_t)b * M * W);
        float eacc = 0.0f;
#pragma unroll 2
        for (int pass = 0; pass < 8; pass++) {
            int mi = pass * 16 + row16;
            int m = slab * 128 + mi;
            float wwm = ww_s[mi];
            float4 v = mem4[m * 16 + l16];
            float4 e = e_s[l16], wv = wv_s[l16];
            float4 nm;
            nm.x = fmaf(v.x, fmaf(-wwm, e.x, 1.0f), wwm * wv.x);
            nm.y = fmaf(v.y, fmaf(-wwm, e.y, 1.0f), wwm * wv.y);
            nm.z = fmaf(v.z, fmaf(-wwm, e.z, 1.0f), wwm * wv.z);
            nm.w = fmaf(v.w, fmaf(-wwm, e.w, 1.0f), wwm * wv.w);
            nm4[m * 16 + l16] = nm;
            float ns = nm.x * nm.x + nm.y * nm.y + nm.z * nm.z + nm.w * nm.w;
            float dr0, dr1, dr2, dr3;
            {
                float4 k0 = rk_s[0 * 16 + l16], k1 = rk_s[1 * 16 + l16];
                float4 k2 = rk_s[2 * 16 + l16], k3 = rk_s[3 * 16 + l16];
                dr0 = nm.x * k0.x + nm.y * k0.y + nm.z * k0.z + nm.w * k0.w;
                dr1 = nm.x * k1.x + nm.y * k1.y + nm.z * k1.z + nm.w * k1.w;
                dr2 = nm.x * k2.x + nm.y * k2.y + nm.z * k2.z + nm.w * k2.w;
                dr3 = nm.x * k3.x + nm.y * k3.y + nm.z * k3.z + nm.w * k3.w;
            }
            float g01 = (l16 & 1) ? dr0 : dr1;
            g01 = __shfl_xor_sync(0xffffffffu, g01, 1);
            float a01 = ((l16 & 1) ? dr1 : dr0) + g01;
            float g23 = (l16 & 1) ? dr2 : dr3;
            g23 = __shfl_xor_sync(0xffffffffu, g23, 1);
            float a23 = ((l16 & 1) ? dr3 : dr2) + g23;
            float gx = (l16 & 2) ? a01 : a23;
            gx = __shfl_xor_sync(0xffffffffu, gx, 2);
            float c = ((l16 & 2) ? a23 : a01) + gx;
            c += __shfl_xor_sync(0xffffffffu, c, 4);
            c += __shfl_xor_sync(0xffffffffu, c, 8);
#pragma unroll
            for (int o = 8; o; o >>= 1) ns += __shfl_xor_sync(0xffffffffu, ns, o);
            if (l16 < 4) {
                float inv = 1.0f / (sqrtf(ns) + 1e-6f);
                float d = c * sk_s[l16] * inv;
                float ev = expf(d - kst_s[l16]);
                g_d[(b * 4 + l16) * M + m] = ev;
                eacc += ev;
            }
        }
        if (l16 < 4) spart[l16 * 16 + row16] = eacc;
        __syncthreads();
        if (t < 4) {
            float s = 0.0f;
#pragma unroll
            for (int i = 0; i < 16; i++) s += spart[t * 16 + i];
            atomicAdd(&g_esum[b * 4 + t], s);
        }
    }
}

// ---------------- K5: nrw + read-vector GEMV ----------------
__global__ __launch_bounds__(1024) void k_gemv(const float* __restrict__ link,
                                               const float* __restrict__ precedence,
                                               const float* __restrict__ read_weights,
                                               float* __restrict__ out) {
    int b = blockIdx.x, t = threadIdx.x;
    __shared__ float nrw_s[4 * M];
    __shared__ float part[4][256];

    {
        int rr = t >> 8, m0 = (t & 255) * 4;
        float4 fw4 = *(const float4*)&g_fw[(b * 4 + rr) * M + m0];
        float4 bw4 = make_float4(0.f, 0.f, 0.f, 0.f);
#pragma unroll
        for (int mt = 0; mt < 16; mt++) {
            float4 p = *(const float4*)&g_bwp[((b * 16 + mt) * 4 + rr) * M + m0];
            bw4.x += p.x; bw4.y += p.y; bw4.z += p.z; bw4.w += p.w;
        }
        float4 ww4 = *(const float4*)&g_ww[b * M + m0];
        float4 pm4 = *(const float4*)&precedence[b * M + m0];
        float4 rw4 = *(const float4*)&read_weights[(b * 4 + rr) * M + m0];
        float4 d4  = *(const float4*)&g_d[(b * 4 + rr) * M + m0];
        float es = g_esum[b * 4 + rr];
        float rm0 = g_rm[b * 12 + rr * 3 + 0];
        float rm1 = g_rm[b * 12 + rr * 3 + 1];
        float rm2 = g_rm[b * 12 + rr * 3 + 2];
        const float* Lb = link + (size_t)b * M * M;
        float fwv[4] = {fw4.x, fw4.y, fw4.z, fw4.w};
        float bwv[4] = {bw4.x, bw4.y, bw4.z, bw4.w};
        float wwv[4] = {ww4.x, ww4.y, ww4.z, ww4.w};
        float pmv[4] = {pm4.x, pm4.y, pm4.z, pm4.w};
        float rwv[4] = {rw4.x, rw4.y, rw4.z, rw4.w};
        float dv4[4] = {d4.x, d4.y, d4.z, d4.w};
#pragma unroll
        for (int k = 0; k < 4; k++) {
            int m = m0 + k;
            float Ld = Lb[(size_t)m * (M + 1)];
            float nld = fmaf(1.0f - 2.0f * wwv[k], Ld, wwv[k] * pmv[k]);
            float corr = nld * rwv[k];
            nrw_s[rr * M + m] = rm0 * (bwv[k] - corr) + rm1 * (fwv[k] - corr) + rm2 * (dv4[k] / es);
        }
    }
    __syncthreads();

    int q = t >> 8;
    int rr = (t >> 6) & 3;
    int wl = t & 63;
    const float* nmB = g_newmem + (size_t)b * M * W + (size_t)q * 256 * W;
    const float* nr = nrw_s + rr * M + q * 256;
    float acc = 0.0f;
#pragma unroll 8
    for (int m = 0; m < 256; m++) acc = fmaf(nr[m], nmB[m * W + wl], acc);
    part[q][rr * 64 + wl] = acc;
    __syncthreads();
    if (t < 256) {
        float s = part[0][t] + part[1][t] + part[2][t] + part[3][t];
        out[b * 256 + t] = s;
    }
}

// ---------------- launch ----------------
extern "C" void kernel_launch(void* const* d_in, const int* in_sizes, int n_in,
                              void* d_out, int out_size) {
    const float* xi   = (const float*)d_in[0];
    const float* Wm   = (const float*)d_in[1];
    const float* bW   = (const float*)d_in[2];
    const float* mem  = (const float*)d_in[3];
    const float* link = (const float*)d_in[4];
    const float* prec = (const float*)d_in[5];
    const float* rw   = (const float*)d_in[6];
    const float* wwo  = (const float*)d_in[7];
    const float* uv   = (const float*)d_in[8];
    float* out = (float*)d_out;

    k_ifprep<<<B, 1024>>>(xi, Wm, bW, rw, wwo, uv);          // 1
    k_wc<<<dim3(8, B), 256>>>(mem);                           // 2
    k_weights<<<B, 1024>>>();                                 // 3
    k_linkmem<<<dim3(24, B), 256>>>(link, prec, rw, mem);     // 4  <- ncu capture slot
    k_gemv<<<B, 1024>>>(link, prec, rw, out);                 // 5
}

// round 11
// speedup vs baseline: 1.0714x; 1.0714x over previous
#include <cuda_runtime.h>
#include <cstdint>
#include <math.h>

#define B   64
#define M   1024
#define W   64
#define R   4
#define D   512
#define IF  471

// ---------------- scratch ----------------
__device__ __align__(16) float g_keys[B * R * W];
__device__ float g_kstr[B * R];
__device__ float g_knorm[B * R];
__device__ __align__(16) float g_wkey[B * W];
__device__ float g_wknorm[B];
__device__ float g_ws[B];
__device__ __align__(16) float g_erase[B * W];
__device__ __align__(16) float g_wvec[B * W];
__device__ float g_ag[B], g_wg[B];
__device__ float g_rm[B * R * 3];
__device__ float g_usage[B * M];
__device__ float g_wcd[B * M];
__device__ float g_ww[B * M];
__device__ float g_d[B * R * M];        // e = exp(d - kstr)
__device__ float g_esum[B * R];
__device__ __align__(16) float g_fw[B * R * M];
__device__ __align__(16) float g_bwp[B * 16 * R * M];
__device__ __align__(16) float g_newmem[B * M * W];

// ---------------- helpers ----------------
__device__ __forceinline__ float sigmoidf_(float x) { return 1.0f / (1.0f + expf(-x)); }
__device__ __forceinline__ float softplusf_(float x) { return (x > 20.0f) ? x : log1pf(expf(x)); }

__device__ __forceinline__ float warpMax_(float v) {
#pragma unroll
    for (int o = 16; o; o >>= 1) v = fmaxf(v, __shfl_xor_sync(0xffffffffu, v, o));
    return v;
}
__device__ __forceinline__ float warpSum_(float v) {
#pragma unroll
    for (int o = 16; o; o >>= 1) v += __shfl_xor_sync(0xffffffffu, v, o);
    return v;
}
__device__ __forceinline__ float blockMax_(float v, float* sh) {
    v = warpMax_(v);
    if ((threadIdx.x & 31) == 0) sh[threadIdx.x >> 5] = v;
    __syncthreads();
    float r = sh[threadIdx.x & 31];
    r = warpMax_(r);
    __syncthreads();
    return r;
}
__device__ __forceinline__ float blockSum_(float v, float* sh) {
    v = warpSum_(v);
    if ((threadIdx.x & 31) == 0) sh[threadIdx.x >> 5] = v;
    __syncthreads();
    float r = sh[threadIdx.x & 31];
    r = warpSum_(r);
    __syncthreads();
    return r;
}

// ---------------- K1: iface GEMV (2-way D-split) + parse + usage ----------------
__global__ __launch_bounds__(1024) void k_ifprep(const float* __restrict__ xi,
                                                 const float* __restrict__ Wm,
                                                 const float* __restrict__ bW,
                                                 const float* __restrict__ read_weights,
                                                 const float* __restrict__ write_weights,
                                                 const float* __restrict__ usage_vector) {
    int b = blockIdx.x, t = threadIdx.x;
    __shared__ float xs[D];
    __shared__ float f[IF + 1];
    __shared__ float fpart[512];
    if (t < D) xs[t] = xi[b * D + t];
    __syncthreads();
    {
        int j = t & 511, half = t >> 9;
        if (j < IF) {
            const float* Wp = Wm + (size_t)(half * 256) * IF + j;
            const float* xh = xs + half * 256;
            float acc = 0.0f;
#pragma unroll 8
            for (int i = 0; i < 256; i++) acc = fmaf(xh[i], Wp[(size_t)i * IF], acc);
            if (half) fpart[j] = acc;
            else      f[j] = acc;
        }
        __syncthreads();
        if (half == 0 && j < IF) f[j] = f[j] + fpart[j] + bW[j];
        __syncthreads();
    }

    if (t < 256) g_keys[b * 256 + t] = f[t];
    if (t >= 256 && t < 320) { int i = t - 256; g_wkey[b * W + i] = f[260 + i]; }
    if (t >= 320 && t < 384) { int i = t - 320; g_erase[b * W + i] = sigmoidf_(f[325 + i]); }
    if (t >= 384 && t < 448) { int i = t - 384; g_wvec[b * W + i] = f[389 + i]; }
    if (t < 4) {
        float x = f[256 + t];
        g_kstr[b * 4 + t] = softplusf_(1.0f + fmaxf(x, 0.0f));
        float s = 0.0f;
        for (int i = 0; i < W; i++) { float v = f[t * W + i]; s = fmaf(v, v, s); }
        g_knorm[b * 4 + t] = sqrtf(s);
        g_esum[b * 4 + t] = 0.0f;
    }
    if (t == 4) {
        float x = f[324];
        g_ws[b] = softplusf_(1.0f + fmaxf(x, 0.0f));
        float s = 0.0f;
        for (int i = 0; i < W; i++) { float v = f[260 + i]; s = fmaf(v, v, s); }
        g_wknorm[b] = sqrtf(s);
    }
    if (t == 5) g_ag[b] = sigmoidf_(f[457]);
    if (t == 6) g_wg[b] = sigmoidf_(f[458]);
    if (t >= 8 && t < 11) {
        int j = t - 8;
        float v[4], mx = -1e30f;
        for (int rr = 0; rr < 4; rr++) { v[rr] = f[458 + rr * 3 + j]; mx = fmaxf(mx, v[rr]); }
        float s = 0.0f;
        for (int rr = 0; rr < 4; rr++) { v[rr] = expf(v[rr] - mx); s += v[rr]; }
        for (int rr = 0; rr < 4; rr++) g_rm[b * 12 + rr * 3 + j] = v[rr] / s;
    }

    float fg0 = sigmoidf_(f[453]), fg1 = sigmoidf_(f[454]);
    float fg2 = sigmoidf_(f[455]), fg3 = sigmoidf_(f[456]);
    for (int m = t; m < M; m += 1024) {
        float uv = usage_vector[b * M + m];
        float wwo = write_weights[b * M + m];
        float u = uv + (1.0f - uv) * wwo;
        float psi = (1.0f - fg0 * read_weights[(b * 4 + 0) * M + m])
                  * (1.0f - fg1 * read_weights[(b * 4 + 1) * M + m])
                  * (1.0f - fg2 * read_weights[(b * 4 + 2) * M + m])
                  * (1.0f - fg3 * read_weights[(b * 4 + 3) * M + m]);
        g_usage[b * M + m] = u * psi;
    }
}

// ---------------- K2: write-content distances (grid 8x64) ----------------
__global__ __launch_bounds__(256) void k_wc(const float* __restrict__ memory) {
    int slab = blockIdx.x, b = blockIdx.y, t = threadIdx.x;
    __shared__ float4 key_s[16];
    __shared__ float sc;
    if (t < 16) key_s[t] = ((const float4*)(g_wkey + b * W))[t];
    if (t == 16) sc = g_ws[b] / (g_wknorm[b] + 1e-6f);
    __syncthreads();
    int row16 = t >> 4, l16 = t & 15;
    const float4* mem4 = (const float4*)(memory + (size_t)b * M * W);
#pragma unroll 2
    for (int pass = 0; pass < 8; pass++) {
        int m = slab * 128 + pass * 16 + row16;
        float4 v = mem4[m * 16 + l16];
        float4 k = key_s[l16];
        float dot = v.x * k.x + v.y * k.y + v.z * k.z + v.w * k.w;
        float ns  = v.x * v.x + v.y * v.y + v.z * v.z + v.w * v.w;
#pragma unroll
        for (int o = 8; o; o >>= 1) {
            dot += __shfl_xor_sync(0xffffffffu, dot, o);
            ns  += __shfl_xor_sync(0xffffffffu, ns, o);
        }
        if (l16 == 0) g_wcd[b * M + m] = dot * sc / (sqrtf(ns) + 1e-6f);
    }
}

// ---------------- K3: softmax(wcd) + allocation sort + ww ----------------
__global__ __launch_bounds__(1024) void k_weights() {
    int b = blockIdx.x, t = threadIdx.x;
    int lane = t & 31, warp = t >> 5;
    __shared__ float dv[M];
    __shared__ float red[32];
    __shared__ unsigned long long ks[M];
    __shared__ float wtot[32];

    {
        float x = g_wcd[b * M + t];
        float mx = blockMax_(x, red);
        float e = expf(x - mx);
        float sm = blockSum_(e, red);
        dv[t] = e / sm;
    }

    float u = 1e-6f + (1.0f - 1e-6f) * g_usage[b * M + t];
    unsigned long long v = ((unsigned long long)__float_as_uint(u) << 32) | (unsigned)t;
#pragma unroll
    for (int k = 2; k <= 32; k <<= 1) {
#pragma unroll
        for (int j = k >> 1; j > 0; j >>= 1) {
            unsigned long long c = __shfl_xor_sync(0xffffffffu, v, j);
            bool keepMin = ((t & j) == 0) == ((t & k) == 0);
            bool less = v < c;
            v = (less == keepMin) ? v : c;
        }
    }
    ks[t] = v;
    __syncthreads();
#pragma unroll
    for (int k = 64; k <= M; k <<= 1) {
        for (int j = k >> 1; j >= 32; j >>= 1) {
            unsigned long long a = ks[t];
            unsigned long long c = ks[t ^ j];
            bool keepMin = ((t & j) == 0) == ((t & k) == 0);
            bool less = a < c;
            v = (less == keepMin) ? a : c;
            __syncthreads();
            ks[t] = v;
            __syncthreads();
        }
#pragma unroll
        for (int j = 16; j > 0; j >>= 1) {
            unsigned long long c = __shfl_xor_sync(0xffffffffu, v, j);
            bool keepMin = ((t & j) == 0) == ((t & k) == 0);
            bool less = v < c;
            v = (less == keepMin) ? v : c;
        }
        if (k < M) { ks[t] = v; __syncthreads(); }
    }
    float su = __uint_as_float((unsigned)(v >> 32));
    float p = su;
#pragma unroll
    for (int o = 1; o < 32; o <<= 1) {
        float q = __shfl_up_sync(0xffffffffu, p, o);
        if (lane >= o) p *= q;
    }
    if (lane == 31) wtot[warp] = p;
    __syncthreads();
    if (warp == 0) {
        float q = wtot[lane];
#pragma unroll
        for (int o = 1; o < 32; o <<= 1) {
            float rr = __shfl_up_sync(0xffffffffu, q, o);
            if (lane >= o) q *= rr;
        }
        wtot[lane] = q;
    }
    __syncthreads();
    if (warp > 0) p *= wtot[warp - 1];

    int idx = (int)(v & 0xffffffffULL);
    float alloc = (1.0f - su) * p;
    float ag = g_ag[b], wg = g_wg[b];
    g_ww[b * M + idx] = wg * (ag * alloc + (1.0f - ag) * dv[idx]);
}

// ---------------- K4: link kernel v6 (cp.async 4-deep pipeline) [PROFILED] ----------------
// G[m,n] = (1-ww[m]-ww[n])*L[m,n] + ww[m]*p[n]  (diag corrected in k_gemv)
// Each thread owns 4 columns; L rows staged via cp.async (16 B/thread/row, 4 stages).
// Threads only read their own staged bytes -> no barriers, wait_group only.
__global__ __launch_bounds__(256) void k_link(const float* __restrict__ link,
                                              const float* __restrict__ precedence,
                                              const float* __restrict__ read_weights) {
    int mt = blockIdx.x;   // 0..15 (64-row tiles)
    int b  = blockIdx.y;
    int t  = threadIdx.x;
    int warp = t >> 5, lane = t & 31;
    __shared__ float ww_row[64];
    __shared__ __align__(16) float4 rw_row[64];
    __shared__ float fw_s[8][4][64];
    __shared__ __align__(16) float stage[4][1024];   // 16 KB, 4 rows in flight

    if (t < 64) ww_row[t] = g_ww[b * M + mt * 64 + t];
    {
        int r = t >> 6, mi = t & 63;
        ((float*)rw_row)[mi * 4 + r] = read_weights[(b * 4 + r) * M + mt * 64 + mi];
    }

    int n0 = t * 4;
    float4 wwn = *(const float4*)&g_ww[b * M + n0];
    float4 pn  = *(const float4*)&precedence[b * M + n0];
    float4 a4  = make_float4(1.0f - wwn.x, 1.0f - wwn.y, 1.0f - wwn.z, 1.0f - wwn.w);
    float4 rwn[4];
#pragma unroll
    for (int rr = 0; rr < 4; rr++) rwn[rr] = *(const float4*)&read_weights[(b * 4 + rr) * M + n0];
    float4 bwa[4];
#pragma unroll
    for (int rr = 0; rr < 4; rr++) bwa[rr] = make_float4(0.f, 0.f, 0.f, 0.f);

    // cp.async pipeline setup
    const float4* Lg = (const float4*)(link + (size_t)b * M * M + (size_t)(mt * 64) * M) + t;
    unsigned int smy;
    {
        void* p = &stage[0][n0];
        smy = (unsigned int)__cvta_generic_to_shared(p);
    }
    // prologue: rows 0..2 into stages 0..2; one commit per row
#pragma unroll
    for (int s = 0; s < 3; s++) {
        asm volatile("cp.async.cg.shared.global [%0], [%1], 16;\n"
                     :: "r"(smy + (unsigned)(s << 12)), "l"(Lg + (size_t)s * 256) : "memory");
        asm volatile("cp.async.commit_group;\n" ::: "memory");
    }
    __syncthreads();   // covers ww_row/rw_row visibility

#pragma unroll 2
    for (int mi = 0; mi < 64; mi++) {
        if (mi + 3 < 64) {
            asm volatile("cp.async.cg.shared.global [%0], [%1], 16;\n"
                         :: "r"(smy + (unsigned)(((mi + 3) & 3) << 12)),
                            "l"(Lg + (size_t)(mi + 3) * 256) : "memory");
        }
        asm volatile("cp.async.commit_group;\n" ::: "memory");
        asm volatile("cp.async.wait_group 3;\n" ::: "memory");

        float4 L = *(const float4*)&stage[mi & 3][n0];
        float wwm = ww_row[mi];
        float4 rr4 = rw_row[mi];
        float nl0 = fmaf(L.x, a4.x - wwm, wwm * pn.x);
        float nl1 = fmaf(L.y, a4.y - wwm, wwm * pn.y);
        float nl2 = fmaf(L.z, a4.z - wwm, wwm * pn.z);
        float nl3 = fmaf(L.w, a4.w - wwm, wwm * pn.w);

        float f0 = nl0 * rwn[0].x + nl1 * rwn[0].y + nl2 * rwn[0].z + nl3 * rwn[0].w;
        float f1 = nl0 * rwn[1].x + nl1 * rwn[1].y + nl2 * rwn[1].z + nl3 * rwn[1].w;
        float f2 = nl0 * rwn[2].x + nl1 * rwn[2].y + nl2 * rwn[2].z + nl3 * rwn[2].w;
        float f3 = nl0 * rwn[3].x + nl1 * rwn[3].y + nl2 * rwn[3].z + nl3 * rwn[3].w;

        bwa[0].x = fmaf(nl0, rr4.x, bwa[0].x); bwa[0].y = fmaf(nl1, rr4.x, bwa[0].y);
        bwa[0].z = fmaf(nl2, rr4.x, bwa[0].z); bwa[0].w = fmaf(nl3, rr4.x, bwa[0].w);
        bwa[1].x = fmaf(nl0, rr4.y, bwa[1].x); bwa[1].y = fmaf(nl1, rr4.y, bwa[1].y);
        bwa[1].z = fmaf(nl2, rr4.y, bwa[1].z); bwa[1].w = fmaf(nl3, rr4.y, bwa[1].w);
        bwa[2].x = fmaf(nl0, rr4.z, bwa[2].x); bwa[2].y = fmaf(nl1, rr4.z, bwa[2].y);
        bwa[2].z = fmaf(nl2, rr4.z, bwa[2].z); bwa[2].w = fmaf(nl3, rr4.z, bwa[2].w);
        bwa[3].x = fmaf(nl0, rr4.w, bwa[3].x); bwa[3].y = fmaf(nl1, rr4.w, bwa[3].y);
        bwa[3].z = fmaf(nl2, rr4.w, bwa[3].z); bwa[3].w = fmaf(nl3, rr4.w, bwa[3].w);

        // packed 6-SHFL reduction: lane L ends with f_{L&3} summed over warp
        float g01 = (lane & 1) ? f0 : f1;
        g01 = __shfl_xor_sync(0xffffffffu, g01, 1);
        float a01s = ((lane & 1) ? f1 : f0) + g01;
        float g23 = (lane & 1) ? f2 : f3;
        g23 = __shfl_xor_sync(0xffffffffu, g23, 1);
        float a23s = ((lane & 1) ? f3 : f2) + g23;
        float gx = (lane & 2) ? a01s : a23s;
        gx = __shfl_xor_sync(0xffffffffu, gx, 2);
        float c = ((lane & 2) ? a23s : a01s) + gx;
        c += __shfl_xor_sync(0xffffffffu, c, 4);
        c += __shfl_xor_sync(0xffffffffu, c, 8);
        c += __shfl_xor_sync(0xffffffffu, c, 16);
        if (lane < 4) fw_s[warp][lane][mi] = c;
    }
    __syncthreads();
    {
        int rr = t >> 6, mi = t & 63;
        float s = 0.0f;
#pragma unroll
        for (int w = 0; w < 8; w++) s += fw_s[w][rr][mi];
        g_fw[(b * 4 + rr) * M + mt * 64 + mi] = s;
    }
#pragma unroll
    for (int rr = 0; rr < 4; rr++)
        *(float4*)&g_bwp[((b * 16 + mt) * 4 + rr) * M + n0] = bwa[rr];
}

// ---------------- K5: memory update + e = exp(d - kstr) + esum ----------------
__global__ __launch_bounds__(256) void k_memup(const float* __restrict__ memory) {
    int slab = blockIdx.x, b = blockIdx.y, t = threadIdx.x;
    __shared__ float ww_s[128];
    __shared__ float4 rk_s[64];
    __shared__ float4 e_s[16], wv_s[16];
    __shared__ float sk_s[4], kst_s[4];
    __shared__ float spart[64];

    if (t < 128) ww_s[t] = g_ww[b * M + slab * 128 + t];
    if (t >= 128 && t < 192) rk_s[t - 128] = ((const float4*)(g_keys + b * 256))[t - 128];
    if (t >= 192 && t < 208) e_s[t - 192] = ((const float4*)(g_erase + b * W))[t - 192];
    if (t >= 208 && t < 224) wv_s[t - 208] = ((const float4*)(g_wvec + b * W))[t - 208];
    if (t >= 224 && t < 228) {
        int r = t - 224;
        float kst = g_kstr[b * 4 + r];
        sk_s[r] = kst / (g_knorm[b * 4 + r] + 1e-6f);
        kst_s[r] = kst;
    }
    __syncthreads();

    int row16 = t >> 4, l16 = t & 15;
    const float4* mem4 = (const float4*)(memory + (size_t)b * M * W);
    float4* nm4 = (float4*)(g_newmem + (size_t)b * M * W);
    float eacc = 0.0f;
#pragma unroll 2
    for (int pass = 0; pass < 8; pass++) {
        int mi = pass * 16 + row16;
        int m = slab * 128 + mi;
        float wwm = ww_s[mi];
        float4 v = mem4[m * 16 + l16];
        float4 e = e_s[l16], wv = wv_s[l16];
        float4 nm;
        nm.x = fmaf(v.x, fmaf(-wwm, e.x, 1.0f), wwm * wv.x);
        nm.y = fmaf(v.y, fmaf(-wwm, e.y, 1.0f), wwm * wv.y);
        nm.z = fmaf(v.z, fmaf(-wwm, e.z, 1.0f), wwm * wv.z);
        nm.w = fmaf(v.w, fmaf(-wwm, e.w, 1.0f), wwm * wv.w);
        nm4[m * 16 + l16] = nm;
        float ns = nm.x * nm.x + nm.y * nm.y + nm.z * nm.z + nm.w * nm.w;
        float dr0, dr1, dr2, dr3;
        {
            float4 k0 = rk_s[0 * 16 + l16], k1 = rk_s[1 * 16 + l16];
            float4 k2 = rk_s[2 * 16 + l16], k3 = rk_s[3 * 16 + l16];
            dr0 = nm.x * k0.x + nm.y * k0.y + nm.z * k0.z + nm.w * k0.w;
            dr1 = nm.x * k1.x + nm.y * k1.y + nm.z * k1.z + nm.w * k1.w;
            dr2 = nm.x * k2.x + nm.y * k2.y + nm.z * k2.z + nm.w * k2.w;
            dr3 = nm.x * k3.x + nm.y * k3.y + nm.z * k3.z + nm.w * k3.w;
        }
        float g01 = (l16 & 1) ? dr0 : dr1;
        g01 = __shfl_xor_sync(0xffffffffu, g01, 1);
        float a01 = ((l16 & 1) ? dr1 : dr0) + g01;
        float g23 = (l16 & 1) ? dr2 : dr3;
        g23 = __shfl_xor_sync(0xffffffffu, g23, 1);
        float a23 = ((l16 & 1) ? dr3 : dr2) + g23;
        float gx = (l16 & 2) ? a01 : a23;
        gx = __shfl_xor_sync(0xffffffffu, gx, 2);
        float c = ((l16 & 2) ? a23 : a01) + gx;
        c += __shfl_xor_sync(0xffffffffu, c, 4);
        c += __shfl_xor_sync(0xffffffffu, c, 8);
#pragma unroll
        for (int o = 8; o; o >>= 1) ns += __shfl_xor_sync(0xffffffffu, ns, o);
        if (l16 < 4) {
            float inv = 1.0f / (sqrtf(ns) + 1e-6f);
            float d = c * sk_s[l16] * inv;
            float ev = expf(d - kst_s[l16]);
            g_d[(b * 4 + l16) * M + m] = ev;
            eacc += ev;
        }
    }
    if (l16 < 4) spart[l16 * 16 + row16] = eacc;
    __syncthreads();
    if (t < 4) {
        float s = 0.0f;
#pragma unroll
        for (int i = 0; i < 16; i++) s += spart[t * 16 + i];
        atomicAdd(&g_esum[b * 4 + t], s);
    }
}

// ---------------- K6: nrw + read-vector GEMV ----------------
__global__ __launch_bounds__(1024) void k_gemv(const float* __restrict__ link,
                                               const float* __restrict__ precedence,
                                               const float* __restrict__ read_weights,
                                               float* __restrict__ out) {
    int b = blockIdx.x, t = threadIdx.x;
    __shared__ float nrw_s[4 * M];
    __shared__ float part[4][256];

    {
        int rr = t >> 8, m0 = (t & 255) * 4;
        float4 fw4 = *(const float4*)&g_fw[(b * 4 + rr) * M + m0];
        float4 bw4 = make_float4(0.f, 0.f, 0.f, 0.f);
#pragma unroll
        for (int mt = 0; mt < 16; mt++) {
            float4 p = *(const float4*)&g_bwp[((b * 16 + mt) * 4 + rr) * M + m0];
            bw4.x += p.x; bw4.y += p.y; bw4.z += p.z; bw4.w += p.w;
        }
        float4 ww4 = *(const float4*)&g_ww[b * M + m0];
        float4 pm4 = *(const float4*)&precedence[b * M + m0];
        float4 rw4 = *(const float4*)&read_weights[(b * 4 + rr) * M + m0];
        float4 d4  = *(const float4*)&g_d[(b * 4 + rr) * M + m0];
        float es = g_esum[b * 4 + rr];
        float rm0 = g_rm[b * 12 + rr * 3 + 0];
        float rm1 = g_rm[b * 12 + rr * 3 + 1];
        float rm2 = g_rm[b * 12 + rr * 3 + 2];
        const float* Lb = link + (size_t)b * M * M;
        float fwv[4] = {fw4.x, fw4.y, fw4.z, fw4.w};
        float bwv[4] = {bw4.x, bw4.y, bw4.z, bw4.w};
        float wwv[4] = {ww4.x, ww4.y, ww4.z, ww4.w};
        float pmv[4] = {pm4.x, pm4.y, pm4.z, pm4.w};
        float rwv[4] = {rw4.x, rw4.y, rw4.z, rw4.w};
        float dv4[4] = {d4.x, d4.y, d4.z, d4.w};
#pragma unroll
        for (int k = 0; k < 4; k++) {
            int m = m0 + k;
            float Ld = Lb[(size_t)m * (M + 1)];
            float nld = fmaf(1.0f - 2.0f * wwv[k], Ld, wwv[k] * pmv[k]);
            float corr = nld * rwv[k];
            nrw_s[rr * M + m] = rm0 * (bwv[k] - corr) + rm1 * (fwv[k] - corr) + rm2 * (dv4[k] / es);
        }
    }
    __syncthreads();

    int q = t >> 8;
    int rr = (t >> 6) & 3;
    int wl = t & 63;
    const float* nmB = g_newmem + (size_t)b * M * W + (size_t)q * 256 * W;
    const float* nr = nrw_s + rr * M + q * 256;
    float acc = 0.0f;
#pragma unroll 8
    for (int m = 0; m < 256; m++) acc = fmaf(nr[m], nmB[m * W + wl], acc);
    part[q][rr * 64 + wl] = acc;
    __syncthreads();
    if (t < 256) {
        float s = part[0][t] + part[1][t] + part[2][t] + part[3][t];
        out[b * 256 + t] = s;
    }
}

// ---------------- launch ----------------
extern "C" void kernel_launch(void* const* d_in, const int* in_sizes, int n_in,
                              void* d_out, int out_size) {
    const float* xi   = (const float*)d_in[0];
    const float* Wm   = (const float*)d_in[1];
    const float* bW   = (const float*)d_in[2];
    const float* mem  = (const float*)d_in[3];
    const float* link = (const float*)d_in[4];
    const float* prec = (const float*)d_in[5];
    const float* rw   = (const float*)d_in[6];
    const float* wwo  = (const float*)d_in[7];
    const float* uv   = (const float*)d_in[8];
    float* out = (float*)d_out;

    k_ifprep<<<B, 1024>>>(xi, Wm, bW, rw, wwo, uv);          // 1
    k_wc<<<dim3(8, B), 256>>>(mem);                           // 2
    k_weights<<<B, 1024>>>();                                 // 3
    k_link<<<dim3(16, B), 256>>>(link, prec, rw);             // 4  <- ncu capture slot
    k_memup<<<dim3(8, B), 256>>>(mem);                        // 5
    k_gemv<<<B, 1024>>>(link, prec, rw, out);                 // 6
}